// round 4
// baseline (speedup 1.0000x reference)
#include <cuda_runtime.h>
#include <math.h>

// RRN sudoku. B=16, N=64, DEG=17, H=96, 32 steps.
// Round 4: step split into msg (gather+3 MLP layers, LDS.128 vectorized),
// lstm (node-tiled gates GEMM + LSTM + pred head), proj (P/Q/Ghh GEMM, 16-node tiles).

#define NSTEP 32
typedef unsigned long long ull;

// ---------- device scratch (allocation-free) ----------
__device__ float g_P[2][1024 * 96];
__device__ float g_Q[1024 * 96];
__device__ float g_Ghh[1024 * 384];
__device__ float g_Xc[1024 * 384];
__device__ float g_s[1024 * 96];
__device__ float g_msg[1024 * 96];
__device__ float g_h2[1024 * 96];
__device__ float g_nodeloss[NSTEP * 1024];
__device__ int   g_nodeok[NSTEP * 1024];

// ---------- packed f32x2 helpers ----------
__device__ __forceinline__ ull pack2(float x, float y) {
    ull r; asm("mov.b64 %0,{%1,%2};" : "=l"(r) : "f"(x), "f"(y)); return r;
}
__device__ __forceinline__ void unpack2(ull v, float& x, float& y) {
    asm("mov.b64 {%0,%1},%2;" : "=f"(x), "=f"(y) : "l"(v));
}
__device__ __forceinline__ void fma2(ull& d, ull a, ull b) {
    asm("fma.rn.f32x2 %0,%1,%2,%0;" : "+l"(d) : "l"(a), "l"(b));
}
__device__ __forceinline__ float sigf(float x) { return 1.f / (1.f + expf(-x)); }

// ---------- 20x96 @ 96x96 column pass; Z transposed ZT[k][r], stride 20 ----------
// rows 0..16 real, 17..19 pad (finite garbage OK: rows never mix).
__device__ __forceinline__ void gemm_pass(const float* Zin, float* Zout,
                                          const float* __restrict__ W,
                                          const float* __restrict__ bias, int c)
{
    ull acc[10];
#pragma unroll
    for (int p = 0; p < 10; p++) acc[p] = 0ull;

#pragma unroll 1
    for (int k0 = 0; k0 < 96; k0 += 8) {
        float w[8];
#pragma unroll
        for (int u = 0; u < 8; u++) w[u] = __ldg(W + (k0 + u) * 96 + c);
#pragma unroll
        for (int u = 0; u < 8; u++) {
            ull w2 = pack2(w[u], w[u]);
            const ulonglong2* zp = (const ulonglong2*)(Zin + (k0 + u) * 20);
            ulonglong2 z0 = zp[0], z1 = zp[1], z2 = zp[2], z3 = zp[3], z4 = zp[4];
            fma2(acc[0], z0.x, w2); fma2(acc[1], z0.y, w2);
            fma2(acc[2], z1.x, w2); fma2(acc[3], z1.y, w2);
            fma2(acc[4], z2.x, w2); fma2(acc[5], z2.y, w2);
            fma2(acc[6], z3.x, w2); fma2(acc[7], z3.y, w2);
            fma2(acc[8], z4.x, w2); fma2(acc[9], z4.y, w2);
        }
    }
    float bv = __ldg(bias + c);
#pragma unroll
    for (int p = 0; p < 10; p++) {
        float x, y; unpack2(acc[p], x, y);
        x = fmaxf(x + bv, 0.f); y = fmaxf(y + bv, 0.f);
        *(ull*)(Zout + c * 20 + 2 * p) = pack2(x, y);
    }
}

// last msg layer: no relu, sum over 17 real rows -> g_msg
__device__ __forceinline__ void gemm_sum(const float* Zin,
                                         const float* __restrict__ W,
                                         const float* __restrict__ bias, int c, int n)
{
    ull acc[9];
#pragma unroll
    for (int p = 0; p < 9; p++) acc[p] = 0ull;

#pragma unroll 1
    for (int k0 = 0; k0 < 96; k0 += 8) {
        float w[8];
#pragma unroll
        for (int u = 0; u < 8; u++) w[u] = __ldg(W + (k0 + u) * 96 + c);
#pragma unroll
        for (int u = 0; u < 8; u++) {
            ull w2 = pack2(w[u], w[u]);
            const ulonglong2* zp = (const ulonglong2*)(Zin + (k0 + u) * 20);
            ulonglong2 z0 = zp[0], z1 = zp[1], z2 = zp[2], z3 = zp[3];
            ull z8 = *(const ull*)(Zin + (k0 + u) * 20 + 16);   // pair 8 (rows 16,17)
            fma2(acc[0], z0.x, w2); fma2(acc[1], z0.y, w2);
            fma2(acc[2], z1.x, w2); fma2(acc[3], z1.y, w2);
            fma2(acc[4], z2.x, w2); fma2(acc[5], z2.y, w2);
            fma2(acc[6], z3.x, w2); fma2(acc[7], z3.y, w2);
            fma2(acc[8], z8,   w2);
        }
    }
    float bv = __ldg(bias + c);
    float s = 17.f * bv;
#pragma unroll
    for (int p = 0; p < 9; p++) {
        float x, y; unpack2(acc[p], x, y);
        s += x;
        if (p < 8) s += y;     // p==8 second lane = pad row 17
    }
    g_msg[n * 96 + c] = s;
}

// ---------- K1: gather + 3 msg layers. CTA == node, thread == column ----------
__global__ void __launch_bounds__(96) msg_kernel(
    int step, const int* __restrict__ edges,
    const float* __restrict__ msg_Ws, const float* __restrict__ msg_bs)
{
    __shared__ float ZTa[96 * 20];
    __shared__ float ZTb[96 * 20];
    __shared__ float sQ[96];
    __shared__ int   sedge[17];

    const int tid = threadIdx.x;
    const int n = blockIdx.x;
    const int j = n & 63;
    const float* Pin = g_P[step & 1];

    if (tid < 17) sedge[tid] = (n & ~63) + __ldg(edges + j * 17 + tid);
    sQ[tid] = g_Q[n * 96 + tid];
    __syncthreads();

    {
        float q = sQ[tid];
        float v[17];
#pragma unroll
        for (int r = 0; r < 17; r++) v[r] = __ldg(Pin + sedge[r] * 96 + tid);
        float* zt = ZTa + tid * 20;
#pragma unroll
        for (int r = 0; r < 17; r++) zt[r] = fmaxf(v[r] + q, 0.f);
        zt[17] = 0.f; zt[18] = 0.f; zt[19] = 0.f;
    }
    __syncthreads();

    gemm_pass(ZTa, ZTb, msg_Ws,         msg_bs,       tid); __syncthreads();
    gemm_pass(ZTb, ZTa, msg_Ws + 9216,  msg_bs + 96,  tid); __syncthreads();
    gemm_sum (ZTa,      msg_Ws + 18432, msg_bs + 192, tid, n);
}

// ---------- K2: gates GEMM (4-node tile) + LSTM + pred head ----------
__global__ void __launch_bounds__(96) lstm_kernel(
    int step, const int* __restrict__ target,
    const float* __restrict__ W_ih,
    const float* __restrict__ pred_W, const float* __restrict__ pred_b,
    float* __restrict__ d_out)
{
    __shared__ float As[96 * 4];     // [k*4 + m]
    __shared__ float h2s[4 * 96];

    const int tid = threadIdx.x;
    const int m0 = blockIdx.x * 4;

#pragma unroll
    for (int m = 0; m < 4; m++)
        As[tid * 4 + m] = g_msg[(m0 + m) * 96 + tid];
    __syncthreads();

    // acc[q][p]: gate q in {i,f,g,o}, node-pair p in {(0,1),(2,3)}
    ull acc[4][2];
#pragma unroll
    for (int q = 0; q < 4; q++) { acc[q][0] = 0ull; acc[q][1] = 0ull; }

#pragma unroll 1
    for (int k0 = 0; k0 < 96; k0 += 4) {
        float w[4][4];
#pragma unroll
        for (int u = 0; u < 4; u++)
#pragma unroll
            for (int q = 0; q < 4; q++)
                w[u][q] = __ldg(W_ih + (k0 + u) * 384 + tid + 96 * q);
#pragma unroll
        for (int u = 0; u < 4; u++) {
            ulonglong2 a = *(const ulonglong2*)(As + (k0 + u) * 4);
#pragma unroll
            for (int q = 0; q < 4; q++) {
                ull w2 = pack2(w[u][q], w[u][q]);
                fma2(acc[q][0], a.x, w2);
                fma2(acc[q][1], a.y, w2);
            }
        }
    }

#pragma unroll
    for (int m = 0; m < 4; m++) {
        int n = m0 + m;
        float g4[4];
#pragma unroll
        for (int q = 0; q < 4; q++) {
            float x, y; unpack2(acc[q][m >> 1], x, y);
            float gv = (m & 1) ? y : x;
            int col = tid + 96 * q;
            g4[q] = gv + __ldg(g_Xc + n * 384 + col) + g_Ghh[n * 384 + col];
        }
        float sp = g_s[n * 96 + tid];
        float s2 = sigf(g4[1]) * sp + sigf(g4[0]) * tanhf(g4[2]);
        float h2 = sigf(g4[3]) * tanhf(s2);
        g_s [n * 96 + tid] = s2;
        g_h2[n * 96 + tid] = h2;
        h2s[m * 96 + tid] = h2;
    }
    __syncthreads();

    // pred head: 32 threads = 4 nodes x 8 digits
    if (tid < 32) {
        int m = tid >> 3, d = tid & 7, n = m0 + m;
        float logit = __ldg(pred_b + d);
        const float* hrow = h2s + m * 96;
#pragma unroll 8
        for (int k = 0; k < 96; k++)
            logit = fmaf(hrow[k], __ldg(pred_W + k * 8 + d), logit);

        float mx = logit;
        for (int off = 4; off; off >>= 1) mx = fmaxf(mx, __shfl_xor_sync(0xffffffffu, mx, off));
        float se = expf(logit - mx);
        for (int off = 4; off; off >>= 1) se += __shfl_xor_sync(0xffffffffu, se, off);
        float lse = mx + logf(se);

        float bl = logit; int bc = d;
        for (int off = 4; off; off >>= 1) {
            float ol = __shfl_xor_sync(0xffffffffu, bl, off);
            int   oc = __shfl_xor_sync(0xffffffffu, bc, off);
            if (ol > bl || (ol == bl && oc < bc)) { bl = ol; bc = oc; }
        }
        int tgt = __ldg(target + n) - 1;
        if (d == tgt) g_nodeloss[step * 1024 + n] = lse - logit;
        if (d == 0) {
            g_nodeok[step * 1024 + n] = (bc == tgt) ? 1 : 0;
            if (step == NSTEP - 1) d_out[33 + n] = (float)bc;
        }
    }
}

// ---------- K3: P / Q / Ghh GEMM from h2, 16-node tiles ----------
// grid (64, 6): sub 0 = P, 1 = Q (+b0), 2..5 = Ghh chunks
__global__ void __launch_bounds__(96) proj_kernel(
    int step,
    const float* __restrict__ msg0_W, const float* __restrict__ msg0_b,
    const float* __restrict__ W_hh)
{
    __shared__ float As[96 * 20];    // [k*20 + m], m 0..15, pad 16..19

    const int tid = threadIdx.x;
    const int m0 = blockIdx.x * 16;
    const int sub = blockIdx.y;

#pragma unroll
    for (int m = 0; m < 16; m++)
        As[tid * 20 + m] = g_h2[(m0 + m) * 96 + tid];
    __syncthreads();

    const float* W; int ldw, colbase = 0;
    if (sub == 0)      { W = msg0_W;          ldw = 96; }
    else if (sub == 1) { W = msg0_W + 9216;   ldw = 96; }
    else               { W = W_hh;            ldw = 384; colbase = (sub - 2) * 96; }
    int col = colbase + tid;

    ull acc[8];
#pragma unroll
    for (int p = 0; p < 8; p++) acc[p] = 0ull;

#pragma unroll 1
    for (int k0 = 0; k0 < 96; k0 += 8) {
        float w[8];
#pragma unroll
        for (int u = 0; u < 8; u++) w[u] = __ldg(W + (k0 + u) * ldw + col);
#pragma unroll
        for (int u = 0; u < 8; u++) {
            ull w2 = pack2(w[u], w[u]);
            const ulonglong2* ap = (const ulonglong2*)(As + (k0 + u) * 20);
            ulonglong2 a0 = ap[0], a1 = ap[1], a2 = ap[2], a3 = ap[3];
            fma2(acc[0], a0.x, w2); fma2(acc[1], a0.y, w2);
            fma2(acc[2], a1.x, w2); fma2(acc[3], a1.y, w2);
            fma2(acc[4], a2.x, w2); fma2(acc[5], a2.y, w2);
            fma2(acc[6], a3.x, w2); fma2(acc[7], a3.y, w2);
        }
    }

    float bias = (sub == 1) ? __ldg(msg0_b + tid) : 0.f;
    float* dst;
    int stride, cc;
    if (sub == 0)      { dst = g_P[(step + 1) & 1]; stride = 96;  cc = tid; }
    else if (sub == 1) { dst = g_Q;                 stride = 96;  cc = tid; }
    else               { dst = g_Ghh;               stride = 384; cc = col; }

#pragma unroll
    for (int p = 0; p < 8; p++) {
        float x, y; unpack2(acc[p], x, y);
        dst[(m0 + 2 * p)     * stride + cc] = x + bias;
        dst[(m0 + 2 * p + 1) * stride + cc] = y + bias;
    }
}

// ---------- prologue: feat -> xin MLP -> Xc; init P/Q/Ghh/s ----------
__global__ void __launch_bounds__(128) prologue_kernel(
    const int* __restrict__ x,
    const float* __restrict__ digit_emb, const float* __restrict__ row_emb,
    const float* __restrict__ col_emb,
    const float* __restrict__ in0_W, const float* __restrict__ in0_b,
    const float* __restrict__ in_Ws, const float* __restrict__ in_bs,
    const float* __restrict__ W_ih, const float* __restrict__ b_ih,
    const float* __restrict__ b_hh, const float* __restrict__ msg0_b)
{
    __shared__ float feat[4][48], va[4][96], vb[4][96];
    int tid = threadIdx.x, lane = tid & 31, w = tid >> 5;
    int n = blockIdx.x * 4 + w;
    int j = n & 63;

    if (lane < 16) {
        int xv = x[n];
        feat[w][lane]      = digit_emb[xv * 16 + lane];
        feat[w][16 + lane] = row_emb[(j >> 3) * 16 + lane];
        feat[w][32 + lane] = col_emb[(j & 7) * 16 + lane];
    }
    __syncwarp();

#pragma unroll
    for (int a = 0; a < 3; a++) {
        int c = lane + 32 * a;
        float acc = in0_b[c];
        for (int k = 0; k < 48; k++) acc = fmaf(feat[w][k], in0_W[k * 96 + c], acc);
        va[w][c] = fmaxf(acc, 0.f);
    }
    __syncwarp();

    for (int l = 0; l < 3; l++) {
        const float* Wl = in_Ws + l * 9216;
        const float* bl = in_bs + l * 96;
        float* src = (l == 1) ? vb[w] : va[w];
        float* dst = (l == 1) ? va[w] : vb[w];
#pragma unroll
        for (int a = 0; a < 3; a++) {
            int c = lane + 32 * a;
            float acc = bl[c];
            for (int k = 0; k < 96; k++) acc = fmaf(src[k], Wl[k * 96 + c], acc);
            dst[c] = (l < 2) ? fmaxf(acc, 0.f) : acc;
        }
        __syncwarp();
    }

    for (int pi = lane; pi < 192; pi += 32) {
        ull acc = 0ull;
#pragma unroll 4
        for (int k = 0; k < 96; k++) {
            ull w2 = __ldg((const ull*)(W_ih + (96 + k) * 384 + 2 * pi));
            float xk = vb[w][k];
            fma2(acc, pack2(xk, xk), w2);
        }
        float xx, yy; unpack2(acc, xx, yy);
        g_Xc[n * 384 + 2 * pi]     = xx + b_ih[2 * pi]     + b_hh[2 * pi];
        g_Xc[n * 384 + 2 * pi + 1] = yy + b_ih[2 * pi + 1] + b_hh[2 * pi + 1];
    }

    for (int t = lane; t < 96; t += 32) {
        g_P[0][n * 96 + t] = 0.f;
        g_Q[n * 96 + t]    = msg0_b[t];
        g_s[n * 96 + t]    = 0.f;
    }
    for (int t = lane; t < 384; t += 32) g_Ghh[n * 384 + t] = 0.f;
}

// ---------- epilogue ----------
__global__ void __launch_bounds__(512) epilogue_kernel(float* __restrict__ d_out)
{
    __shared__ int   cnt[32];
    __shared__ float red[512];
    int tid = threadIdx.x;
    if (tid < 32) cnt[tid] = 0;
    __syncthreads();

    int s = tid >> 4, b = tid & 15;
    int ok = 1;
    for (int jj = 0; jj < 64; jj++) ok &= g_nodeok[s * 1024 + b * 64 + jj];
    atomicAdd(&cnt[s], ok);

    float ls = 0.f;
    for (int i = tid; i < NSTEP * 1024; i += 512) ls += g_nodeloss[i];
    red[tid] = ls;
    __syncthreads();
    for (int off = 256; off; off >>= 1) {
        if (tid < off) red[tid] += red[tid + off];
        __syncthreads();
    }
    if (tid == 0)  d_out[0] = red[0] / (1024.f * 32.f);
    if (tid < 32)  d_out[1 + tid] = cnt[tid] * (1.f / 16.f);
}

// ---------- launch ----------
extern "C" void kernel_launch(void* const* d_in, const int* in_sizes, int n_in,
                              void* d_out, int out_size)
{
    (void)in_sizes; (void)n_in; (void)out_size;
    const int*   x         = (const int*)  d_in[0];
    const int*   target    = (const int*)  d_in[1];
    const int*   edges     = (const int*)  d_in[2];
    const float* digit_emb = (const float*)d_in[3];
    const float* row_emb   = (const float*)d_in[4];
    const float* col_emb   = (const float*)d_in[5];
    const float* in0_W     = (const float*)d_in[6];
    const float* in0_b     = (const float*)d_in[7];
    const float* in_Ws     = (const float*)d_in[8];
    const float* in_bs     = (const float*)d_in[9];
    const float* msg0_W    = (const float*)d_in[10];
    const float* msg0_b    = (const float*)d_in[11];
    const float* msg_Ws    = (const float*)d_in[12];
    const float* msg_bs    = (const float*)d_in[13];
    const float* W_ih      = (const float*)d_in[14];
    const float* W_hh      = (const float*)d_in[15];
    const float* b_ih      = (const float*)d_in[16];
    const float* b_hh      = (const float*)d_in[17];
    const float* pred_W    = (const float*)d_in[18];
    const float* pred_b    = (const float*)d_in[19];
    float* out = (float*)d_out;

    prologue_kernel<<<256, 128>>>(x, digit_emb, row_emb, col_emb,
                                  in0_W, in0_b, in_Ws, in_bs,
                                  W_ih, b_ih, b_hh, msg0_b);
    for (int s = 0; s < NSTEP; s++) {
        msg_kernel <<<1024, 96>>>(s, edges, msg_Ws, msg_bs);
        lstm_kernel<<<256, 96>>>(s, target, W_ih, pred_W, pred_b, out);
        if (s < NSTEP - 1)
            proj_kernel<<<dim3(64, 6), 96>>>(s, msg0_W, msg0_b, W_hh);
    }
    epilogue_kernel<<<1, 512>>>(out);
}